// round 2
// baseline (speedup 1.0000x reference)
#include <cuda_runtime.h>
#include <cstdint>

#define BB 32
#define TT 512
#define II 128
#define HH 1024
#define GG 4096
#define OO 128

#define NBLK 260
#define NTH 256
#define CHUNK 64

// ---------------- device scratch (no allocations allowed) ----------------
__device__ float Wp_ih0[II * GG];   // [k][n] permuted: n = j*4+g
__device__ float Wp_hh0[HH * GG];
__device__ float Wp_ih1[HH * GG];
__device__ float Wp_hh1[HH * GG];
__device__ float Wp_out[HH * OO];   // [k][o]
__device__ float bp0[GG];
__device__ float bp1[GG];
__device__ float h0s[2][BB][HH];    // layer0 hidden (double-buffered)
__device__ float h2s[2][BB][HH];    // layer1 hidden (double-buffered)
__device__ float c0s[BB][HH];
__device__ float c1s[BB][HH];
__device__ unsigned g_bar;

// ---------------- init: zero states + barrier ----------------
__global__ void init_kernel() {
    int idx = blockIdx.x * blockDim.x + threadIdx.x;
    int stride = gridDim.x * blockDim.x;
    float* p0 = &h0s[0][0][0];
    float* p1 = &h2s[0][0][0];
    for (int i = idx; i < 2 * BB * HH; i += stride) { p0[i] = 0.f; p1[i] = 0.f; }
    float* p2 = &c0s[0][0];
    float* p3 = &c1s[0][0];
    for (int i = idx; i < BB * HH; i += stride) { p2[i] = 0.f; p3[i] = 0.f; }
    if (idx == 0) g_bar = 0u;
}

// ---------------- prep: transpose + gate-permute weights ----------------
__global__ void prep_kernel(const float* __restrict__ Wih0, const float* __restrict__ Whh0,
                            const float* __restrict__ b0v, const float* __restrict__ Wih1,
                            const float* __restrict__ Whh1, const float* __restrict__ b1v,
                            const float* __restrict__ Wout) {
    const int S0 = II * GG;      // 524288
    const int S1 = HH * GG;      // 4194304
    const int S4 = HH * OO;      // 131072
    const int total = S0 + 3 * S1 + S4 + 2 * GG;
    int stride = gridDim.x * blockDim.x;
    for (int idx = blockIdx.x * blockDim.x + threadIdx.x; idx < total; idx += stride) {
        int r = idx;
        if (r < S0) {
            int k = r >> 12, n = r & (GG - 1);
            int g = n & 3, j = n >> 2;
            Wp_ih0[r] = Wih0[(g * HH + j) * II + k];
        } else if ((r -= S0) < S1) {
            int k = r >> 12, n = r & (GG - 1);
            int g = n & 3, j = n >> 2;
            Wp_hh0[r] = Whh0[(g * HH + j) * HH + k];
        } else if ((r -= S1) < S1) {
            int k = r >> 12, n = r & (GG - 1);
            int g = n & 3, j = n >> 2;
            Wp_ih1[r] = Wih1[(g * HH + j) * HH + k];
        } else if ((r -= S1) < S1) {
            int k = r >> 12, n = r & (GG - 1);
            int g = n & 3, j = n >> 2;
            Wp_hh1[r] = Whh1[(g * HH + j) * HH + k];
        } else if ((r -= S1) < S4) {
            int k = r >> 7, o = r & (OO - 1);
            Wp_out[r] = Wout[o * HH + k];
        } else if ((r -= S4) < GG) {
            int g = r & 3, j = r >> 2;
            bp0[r] = b0v[g * HH + j];
        } else {
            r -= GG;
            int g = r & 3, j = r >> 2;
            bp1[r] = b1v[g * HH + j];
        }
    }
}

// ---------------- packed fp32x2 FMA ----------------
#define FMA2(acc, a, b) asm("fma.rn.f32x2 %0, %1, %2, %0;" : "+l"(acc) : "l"(a), "l"(b))

__device__ __forceinline__ float sigf(float x) { return 1.0f / (1.0f + __expf(-x)); }

__device__ __forceinline__ float2 up64(unsigned long long v) {
    float2 f;
    f.x = __uint_as_float((unsigned)v);
    f.y = __uint_as_float((unsigned)(v >> 32));
    return f;
}

// ROLE 0 = layer0 step (K=128 x + 1024 h), ROLE 1 = layer1 step (K=1024+1024),
// ROLE 2 = output head (K=1024)
template <int ROLE>
__device__ __forceinline__ void do_pass(int p, int t, int cg, int tid,
                                        unsigned long long (*tile)[CHUNK][33],
                                        const float* __restrict__ x,
                                        const float* __restrict__ b_out,
                                        float* __restrict__ out) {
    const int ng = tid & 7;           // 8 column-quads of 4
    const int bg = (tid >> 3) & 15;   // 16 batch pairs
    const int ks = tid >> 7;          // k-split half
    const int b0 = bg * 2;
    const int colbase = cg * 32;
    const int n0 = colbase + ng * 4;
    const int par = p & 1, prev = par ^ 1;

    constexpr int K2 = (ROLE == 0) ? 576 : (ROLE == 1) ? 1024 : 512;
    constexpr int NCH = K2 / CHUNK;
    constexpr int WS = (ROLE == 2) ? OO : GG;

    const float* __restrict__ hA = &h0s[prev][0][0];
    const float* __restrict__ hB = &h2s[prev][0][0];

    unsigned long long a00 = 0, a01 = 0, a10 = 0, a11 = 0;

    for (int c = 0; c < NCH; ++c) {
        __syncthreads();
        // stage both k-slices' chunks into smem, transposed + lane-duplicated
        #pragma unroll
        for (int u = 0; u < (2 * CHUNK * 32) / NTH; ++u) {
            int idx = tid + u * NTH;
            int ii = idx & 63;
            int bb = (idx >> 6) & 31;
            int ss = idx >> 11;
            int k = ss * K2 + c * CHUNK + ii;
            float v;
            if (ROLE == 0)
                v = (k < II) ? __ldg(&x[(bb * TT + t) * II + k]) : __ldcg(&hA[bb * HH + (k - II)]);
            else if (ROLE == 1)
                v = (k < HH) ? __ldcg(&hA[bb * HH + k]) : __ldcg(&hB[bb * HH + (k - HH)]);
            else
                v = __ldcg(&hB[bb * HH + k]);
            unsigned ui = __float_as_uint(v);
            tile[ss][ii][bb] = (unsigned long long)ui | ((unsigned long long)ui << 32);
        }
        __syncthreads();

        int kb = ks * K2 + c * CHUNK;
        const float* W;
        if (ROLE == 0)
            W = (kb < II) ? (Wp_ih0 + (size_t)kb * GG) : (Wp_hh0 + (size_t)(kb - II) * GG);
        else if (ROLE == 1)
            W = (kb < HH) ? (Wp_ih1 + (size_t)kb * GG) : (Wp_hh1 + (size_t)(kb - HH) * GG);
        else
            W = Wp_out + (size_t)kb * OO;
        const float* wp = W + n0;

        #pragma unroll 8
        for (int i = 0; i < CHUNK; ++i) {
            ulonglong2 w = *reinterpret_cast<const ulonglong2*>(wp + (size_t)i * WS);
            unsigned long long t0 = tile[ks][i][b0];
            unsigned long long t1 = tile[ks][i][b0 + 1];
            FMA2(a00, w.x, t0);   // (n0,n1) x b0
            FMA2(a01, w.x, t1);   // (n0,n1) x b1
            FMA2(a10, w.y, t0);   // (n2,n3) x b0
            FMA2(a11, w.y, t1);   // (n2,n3) x b1
        }
    }

    // k-split reduction through smem (reuse tile)
    __syncthreads();
    float* red = reinterpret_cast<float*>(tile);
    {
        float2 f;
        f = up64(a00); red[tid * 8 + 0] = f.x; red[tid * 8 + 1] = f.y;
        f = up64(a01); red[tid * 8 + 2] = f.x; red[tid * 8 + 3] = f.y;
        f = up64(a10); red[tid * 8 + 4] = f.x; red[tid * 8 + 5] = f.y;
        f = up64(a11); red[tid * 8 + 6] = f.x; red[tid * 8 + 7] = f.y;
    }
    __syncthreads();
    if (ks == 0) {
        float s[8];
        #pragma unroll
        for (int q = 0; q < 8; ++q) s[q] = red[tid * 8 + q] + red[(tid + 128) * 8 + q];

        if (ROLE < 2) {
            const float* bp = (ROLE == 0) ? bp0 : bp1;
            float* cst = (ROLE == 0) ? &c0s[0][0] : &c1s[0][0];
            float* hdst = (ROLE == 0) ? &h0s[par][0][0] : &h2s[par][0][0];
            int j = n0 >> 2;
            float bi_ = bp[n0], bf_ = bp[n0 + 1], bg_ = bp[n0 + 2], bo_ = bp[n0 + 3];
            {   // batch b0: i=s0, f=s1, g=s4, o=s5
                float ig = s[0] + bi_, fg = s[1] + bf_, gg = s[4] + bg_, og = s[5] + bo_;
                float cold = cst[b0 * HH + j];
                float cn = sigf(fg) * cold + sigf(ig) * tanhf(gg);
                cst[b0 * HH + j] = cn;
                __stcg(&hdst[b0 * HH + j], sigf(og) * tanhf(cn));
            }
            {   // batch b0+1: i=s2, f=s3, g=s6, o=s7
                float ig = s[2] + bi_, fg = s[3] + bf_, gg = s[6] + bg_, og = s[7] + bo_;
                float cold = cst[(b0 + 1) * HH + j];
                float cn = sigf(fg) * cold + sigf(ig) * tanhf(gg);
                cst[(b0 + 1) * HH + j] = cn;
                __stcg(&hdst[(b0 + 1) * HH + j], sigf(og) * tanhf(cn));
            }
        } else {
            float w0 = b_out[n0], w1 = b_out[n0 + 1], w2 = b_out[n0 + 2], w3 = b_out[n0 + 3];
            float* o0 = out + ((size_t)b0 * TT + t) * OO + n0;
            o0[0] = s[0] + w0; o0[1] = s[1] + w1; o0[2] = s[4] + w2; o0[3] = s[5] + w3;
            float* o1 = out + ((size_t)(b0 + 1) * TT + t) * OO + n0;
            o1[0] = s[2] + w0; o1[1] = s[3] + w1; o1[2] = s[6] + w2; o1[3] = s[7] + w3;
        }
    }
}

// ---------------- persistent pipelined kernel ----------------
__global__ void __launch_bounds__(NTH, 2) lstm_kernel(const float* __restrict__ x,
                                                      const float* __restrict__ b_out,
                                                      float* __restrict__ out) {
    __shared__ unsigned long long tile[2][CHUNK][33];
    const int tid = threadIdx.x;
    const int bid = blockIdx.x;

    int role, cg;
    if (bid < 128)      { role = 0; cg = bid; }
    else if (bid < 256) { role = 1; cg = bid - 128; }
    else                { role = 2; cg = bid - 256; }

    for (int p = 0; p < TT + 2; ++p) {
        if (role == 0) {
            if (p < TT) do_pass<0>(p, p, cg, tid, tile, x, b_out, out);
        } else if (role == 1) {
            if (p >= 1 && p <= TT) do_pass<1>(p, p - 1, cg, tid, tile, x, b_out, out);
        } else {
            if (p >= 2) do_pass<2>(p, p - 2, cg, tid, tile, x, b_out, out);
        }
        // ---- grid barrier (all 260 blocks guaranteed co-resident) ----
        __threadfence();
        __syncthreads();
        if (tid == 0) {
            atomicAdd(&g_bar, 1u);
            unsigned target = (unsigned)(p + 1) * NBLK;
            while (*((volatile unsigned*)&g_bar) < target) __nanosleep(64);
        }
        __syncthreads();
    }
}

// ---------------- launch ----------------
extern "C" void kernel_launch(void* const* d_in, const int* in_sizes, int n_in,
                              void* d_out, int out_size) {
    const float* x     = (const float*)d_in[0];
    const float* Wih0  = (const float*)d_in[1];
    const float* Whh0  = (const float*)d_in[2];
    const float* b0v   = (const float*)d_in[3];
    const float* Wih1  = (const float*)d_in[4];
    const float* Whh1  = (const float*)d_in[5];
    const float* b1v   = (const float*)d_in[6];
    const float* Wout  = (const float*)d_in[7];
    const float* boutv = (const float*)d_in[8];
    float* out = (float*)d_out;

    init_kernel<<<256, 256>>>();
    prep_kernel<<<512, 256>>>(Wih0, Whh0, b0v, Wih1, Whh1, b1v, Wout);
    lstm_kernel<<<NBLK, NTH>>>(x, boutv, out);
}

// round 4
// speedup vs baseline: 1.6371x; 1.6371x over previous
#include <cuda_runtime.h>
#include <cstdint>

#define BB 32
#define TT 512
#define II 128
#define HH 1024
#define GG 4096
#define OO 128

#define NTH 256
#define NBLK 276
#define CH 128
#define PAD 68     // floats per tile row: 64 data + 4 pad
#define RPAD 18    // u64 per reduction row: 16 data + 2 pad (16B aligned)

// ---------------- device scratch ----------------
__device__ float Wp_ih0[II * GG];   // [k][n], n = j*4+g
__device__ float Wp_hh0[HH * GG];
__device__ float Wp_ih1[HH * GG];
__device__ float Wp_hh1[HH * GG];
__device__ float Wp_out[HH * OO];   // [k][o]
__device__ float gb0[GG];
__device__ float gb1[GG];
__device__ float h0s[2][HH][BB];    // layer0 hidden, transposed [j][b], double-buffered
__device__ float h2s[2][HH][BB];    // layer1 hidden
__device__ unsigned g_cnt;
__device__ unsigned g_flag;

// ---------------- prep: reset states/barrier + permute weights ----------------
__global__ void prep_kernel(const float* __restrict__ Wih0, const float* __restrict__ Whh0,
                            const float* __restrict__ b0v, const float* __restrict__ Wih1,
                            const float* __restrict__ Whh1, const float* __restrict__ b1v,
                            const float* __restrict__ Wout) {
    int idx0 = blockIdx.x * blockDim.x + threadIdx.x;
    int stride = gridDim.x * blockDim.x;
    if (idx0 == 0) { g_cnt = 0u; g_flag = 0u; }
    float* hz0 = &h0s[0][0][0];
    float* hz1 = &h2s[0][0][0];
    for (int i = idx0; i < 2 * HH * BB; i += stride) { hz0[i] = 0.f; hz1[i] = 0.f; }

    const int S0 = II * GG;
    const int S1 = HH * GG;
    const int S4 = HH * OO;
    const int total = S0 + 3 * S1 + S4 + 2 * GG;
    for (int idx = idx0; idx < total; idx += stride) {
        int r = idx;
        if (r < S0) {
            int k = r >> 12, n = r & (GG - 1);
            int g = n & 3, j = n >> 2;
            Wp_ih0[r] = Wih0[(g * HH + j) * II + k];
        } else if ((r -= S0) < S1) {
            int k = r >> 12, n = r & (GG - 1);
            int g = n & 3, j = n >> 2;
            Wp_hh0[r] = Whh0[(g * HH + j) * HH + k];
        } else if ((r -= S1) < S1) {
            int k = r >> 12, n = r & (GG - 1);
            int g = n & 3, j = n >> 2;
            Wp_ih1[r] = Wih1[(g * HH + j) * HH + k];
        } else if ((r -= S1) < S1) {
            int k = r >> 12, n = r & (GG - 1);
            int g = n & 3, j = n >> 2;
            Wp_hh1[r] = Whh1[(g * HH + j) * HH + k];
        } else if ((r -= S1) < S4) {
            Wp_out[r] = Wout[(r & (OO - 1)) * HH + (r >> 7)];
        } else if ((r -= S4) < GG) {
            gb0[r] = b0v[(r & 3) * HH + (r >> 2)];
        } else {
            r -= GG;
            gb1[r] = b1v[(r & 3) * HH + (r >> 2)];
        }
    }
}

// ---------------- packed fp32x2 ops ----------------
#define FMA2(acc, a, b) asm("fma.rn.f32x2 %0, %1, %2, %0;" : "+l"(acc) : "l"(a), "l"(b))
#define ADD2(acc, a)    asm("add.rn.f32x2 %0, %0, %1;" : "+l"(acc) : "l"(a))

__device__ __forceinline__ float sigf(float x) { return 1.0f / (1.0f + __expf(-x)); }
__device__ __forceinline__ float tanhfast(float x) {
    return 1.0f - __fdividef(2.0f, __expf(2.0f * x) + 1.0f);
}
__device__ __forceinline__ float2 u2f(unsigned long long v) {
    float2 f;
    f.x = __uint_as_float((unsigned)v);
    f.y = __uint_as_float((unsigned)(v >> 32));
    return f;
}

// ---------------- grid barrier (sense/epoch) ----------------
__device__ __forceinline__ void grid_bar(int p) {
    if (threadIdx.x < 32) __threadfence();   // global writers are warp 0
    __syncthreads();
    if (threadIdx.x == 0) {
        unsigned tgt = (unsigned)(p + 1);
        unsigned old = atomicAdd(&g_cnt, 1u);
        if (old == tgt * NBLK - 1u) {
            asm volatile("st.global.release.gpu.u32 [%0], %1;" :: "l"(&g_flag), "r"(tgt) : "memory");
        } else {
            unsigned v;
            do {
                asm volatile("ld.global.acquire.gpu.u32 %0, [%1];" : "=r"(v) : "l"(&g_flag) : "memory");
                if (v >= tgt) break;
                __nanosleep(128);
            } while (true);
        }
    }
    __syncthreads();
}

// ROLE 0 = layer0 (K = 128 x + 1024 h, NCH=9)
// ROLE 1 = layer1 (K = 1024 + 1024,    NCH=16)
// ROLE 2 = head   (K = 1024,           NCH=8)
template <int ROLE, int NCH>
__device__ __forceinline__ void do_pass(int p, int t, int cg, float* tilef,
                                        const float* __restrict__ x,
                                        const float* __restrict__ b_out,
                                        float* __restrict__ out,
                                        float* creg) {
    const int tid = threadIdx.x;
    const int ks = tid >> 5;          // warp index = k-split (8)
    const int lane = tid & 31;
    const int bg = lane >> 2;         // 8 batch groups of 4
    const int ng = lane & 3;          // 4 col groups of 8
    const int n0 = cg * 32 + ng * 8;
    const int b0 = bg * 4;
    const int par = p & 1, prev = par ^ 1;

    constexpr int WS = (ROLE == 2) ? OO : GG;

    const float* __restrict__ hA = &h0s[prev][0][0];
    const float* __restrict__ hB = &h2s[prev][0][0];

    unsigned long long acc[4][4];
#pragma unroll
    for (int i = 0; i < 4; ++i)
#pragma unroll
        for (int j = 0; j < 4; ++j) acc[i][j] = 0ull;

    for (int c = 0; c < NCH; ++c) {
        const float* src = hB;
        const float* wbase = Wp_out;
        int koff = c * CH;
        if (ROLE == 0) {
            if (c == 0) { wbase = Wp_ih0; koff = 0; }
            else        { src = hA; wbase = Wp_hh0; koff = c * CH - II; }
        } else if (ROLE == 1) {
            if (c < 8)  { src = hA; wbase = Wp_ih1; koff = c * CH; }
            else        { src = hB; wbase = Wp_hh1; koff = c * CH - HH; }
        }

        __syncthreads();
        if (ROLE == 0 && c == 0) {
            // stage x[:, t, :] (k = 0..127), duplicate each value into a pair
            const int kkx = tid & 127;
            const int bpx = tid >> 7;
            const float* xb = x + (size_t)t * II + kkx;
#pragma unroll
            for (int u = 0; u < 8; ++u) {
                int bp = bpx + 2 * u;
                float v0 = __ldg(xb + (size_t)(2 * bp) * TT * II);
                float v1 = __ldg(xb + (size_t)(2 * bp + 1) * TT * II);
                uint4 d;
                d.x = d.y = __float_as_uint(v0);
                d.z = d.w = __float_as_uint(v1);
                *reinterpret_cast<uint4*>(&tilef[kkx * PAD + bp * 4]) = d;
            }
        } else {
            // stage h chunk (transposed [k][b]) with pair duplication
            const int bp = tid & 15;
            const int kk0 = tid >> 4;
            const float* sp = src + (size_t)(koff + kk0) * BB + bp * 2;
            float* dp = &tilef[kk0 * PAD + bp * 4];
#pragma unroll
            for (int u = 0; u < 8; ++u) {
                float2 v = __ldcg(reinterpret_cast<const float2*>(sp));
                uint4 d;
                d.x = d.y = __float_as_uint(v.x);
                d.z = d.w = __float_as_uint(v.y);
                *reinterpret_cast<uint4*>(dp) = d;
                sp += 16 * BB;
                dp += 16 * PAD;
            }
        }
        __syncthreads();

        const float* wrow = wbase + (size_t)(koff + ks) * WS + n0;
        const float* hrow = &tilef[ks * PAD + bg * 8];
#pragma unroll 4
        for (int tt = 0; tt < CH / 8; ++tt) {
            ulonglong2 w0 = *reinterpret_cast<const ulonglong2*>(wrow);
            ulonglong2 w1 = *reinterpret_cast<const ulonglong2*>(wrow + 4);
            ulonglong2 ha = *reinterpret_cast<const ulonglong2*>(hrow);
            ulonglong2 hb = *reinterpret_cast<const ulonglong2*>(hrow + 4);
            FMA2(acc[0][0], w0.x, ha.x); FMA2(acc[0][1], w0.x, ha.y);
            FMA2(acc[0][2], w0.x, hb.x); FMA2(acc[0][3], w0.x, hb.y);
            FMA2(acc[1][0], w0.y, ha.x); FMA2(acc[1][1], w0.y, ha.y);
            FMA2(acc[1][2], w0.y, hb.x); FMA2(acc[1][3], w0.y, hb.y);
            FMA2(acc[2][0], w1.x, ha.x); FMA2(acc[2][1], w1.x, ha.y);
            FMA2(acc[2][2], w1.x, hb.x); FMA2(acc[2][3], w1.x, hb.y);
            FMA2(acc[3][0], w1.y, ha.x); FMA2(acc[3][1], w1.y, ha.y);
            FMA2(acc[3][2], w1.y, hb.x); FMA2(acc[3][3], w1.y, hb.y);
            wrow += 8 * WS;
            hrow += 8 * PAD;
        }
    }

    // ---- k-split reduction through smem ----
    __syncthreads();
    unsigned long long* red = reinterpret_cast<unsigned long long*>(tilef);
    unsigned long long* myrow = red + (size_t)tid * RPAD;
#pragma unroll
    for (int q = 0; q < 4; ++q) {
        ulonglong2 v0, v1;
        v0.x = acc[q][0]; v0.y = acc[q][1];
        v1.x = acc[q][2]; v1.y = acc[q][3];
        *reinterpret_cast<ulonglong2*>(myrow + q * 4) = v0;
        *reinterpret_cast<ulonglong2*>(myrow + q * 4 + 2) = v1;
    }
    __syncthreads();
    if (ks == 0) {
        unsigned long long s[16];
#pragma unroll
        for (int q = 0; q < 16; ++q) s[q] = 0ull;
#pragma unroll
        for (int w = 0; w < 8; ++w) {
            unsigned long long* rp = red + (size_t)(w * 32 + lane) * RPAD;
#pragma unroll
            for (int m = 0; m < 8; ++m) {
                ulonglong2 v = *reinterpret_cast<ulonglong2*>(rp + m * 2);
                ADD2(s[m * 2], v.x);
                ADD2(s[m * 2 + 1], v.y);
            }
        }
        // s[4q+bi]: col-pair q of {(i,f)j0,(g,o)j0,(i,f)j1,(g,o)j1}, batch b0+bi

        if (ROLE < 2) {
            const float* gbv = (ROLE == 0) ? gb0 : gb1;
            float* hdst = (ROLE == 0) ? &h0s[par][0][0] : &h2s[par][0][0];
            const int j0 = n0 >> 2;
#pragma unroll
            for (int jj = 0; jj < 2; ++jj) {
                float bi_ = gbv[n0 + jj * 4 + 0];
                float bf_ = gbv[n0 + jj * 4 + 1];
                float bg_ = gbv[n0 + jj * 4 + 2];
                float bo_ = gbv[n0 + jj * 4 + 3];
                float hv[4];
#pragma unroll
                for (int bi = 0; bi < 4; ++bi) {
                    float2 gif = u2f(s[(2 * jj) * 4 + bi]);      // (i, f)
                    float2 ggo = u2f(s[(2 * jj + 1) * 4 + bi]);  // (g, o)
                    float ig = sigf(gif.x + bi_);
                    float fg = sigf(gif.y + bf_);
                    float gt = tanhfast(ggo.x + bg_);
                    float og = sigf(ggo.y + bo_);
                    float cn = fg * creg[jj * 4 + bi] + ig * gt;
                    creg[jj * 4 + bi] = cn;
                    hv[bi] = og * tanhfast(cn);
                }
                float4 hq = make_float4(hv[0], hv[1], hv[2], hv[3]);
                __stcg(reinterpret_cast<float4*>(&hdst[(size_t)(j0 + jj) * BB + b0]), hq);
            }
        } else {
            float bo[8];
#pragma unroll
            for (int q = 0; q < 8; ++q) bo[q] = b_out[n0 + q];
#pragma unroll
            for (int bi = 0; bi < 4; ++bi) {
                float2 p0 = u2f(s[0 * 4 + bi]);
                float2 p1 = u2f(s[1 * 4 + bi]);
                float2 p2 = u2f(s[2 * 4 + bi]);
                float2 p3 = u2f(s[3 * 4 + bi]);
                float4 lo = make_float4(p0.x + bo[0], p0.y + bo[1], p1.x + bo[2], p1.y + bo[3]);
                float4 hi = make_float4(p2.x + bo[4], p2.y + bo[5], p3.x + bo[6], p3.y + bo[7]);
                float* op = out + ((size_t)(b0 + bi) * TT + t) * OO + n0;
                *reinterpret_cast<float4*>(op) = lo;
                *reinterpret_cast<float4*>(op + 4) = hi;
            }
        }
    }
}

// ---------------- persistent pipelined kernel ----------------
__global__ void __launch_bounds__(NTH, 2) lstm_kernel(const float* __restrict__ x,
                                                      const float* __restrict__ b_out,
                                                      float* __restrict__ out) {
    __shared__ __align__(16) float tilef[9216];   // 36864 B: tile (8704 f) | reduction (9216 f)
    const int bid = blockIdx.x;
    float creg[8];
#pragma unroll
    for (int i = 0; i < 8; ++i) creg[i] = 0.f;

    if (bid < 128) {
        // layer 0: t = p
        for (int p = 0; p < TT + 2; ++p) {
            if (p < TT) do_pass<0, 9>(p, p, bid, tilef, x, b_out, out, creg);
            grid_bar(p);
        }
    } else if (bid < 132) {
        // head: t = p - 2
        for (int p = 0; p < TT + 2; ++p) {
            if (p >= 2) do_pass<2, 8>(p, p - 2, bid - 128, tilef, x, b_out, out, creg);
            grid_bar(p);
        }
    } else if (bid < 148) {
        // idle (keeps barrier count uniform)
        for (int p = 0; p < TT + 2; ++p) grid_bar(p);
    } else {
        // layer 1: t = p - 1 (pairs with layer-0 block bid-148 on the same SM)
        for (int p = 0; p < TT + 2; ++p) {
            if (p >= 1 && p <= TT) do_pass<1, 16>(p, p - 1, bid - 148, tilef, x, b_out, out, creg);
            grid_bar(p);
        }
    }
}

// ---------------- launch ----------------
extern "C" void kernel_launch(void* const* d_in, const int* in_sizes, int n_in,
                              void* d_out, int out_size) {
    const float* x     = (const float*)d_in[0];
    const float* Wih0  = (const float*)d_in[1];
    const float* Whh0  = (const float*)d_in[2];
    const float* b0v   = (const float*)d_in[3];
    const float* Wih1  = (const float*)d_in[4];
    const float* Whh1  = (const float*)d_in[5];
    const float* b1v   = (const float*)d_in[6];
    const float* Wout  = (const float*)d_in[7];
    const float* boutv = (const float*)d_in[8];
    float* out = (float*)d_out;

    prep_kernel<<<512, 256>>>(Wih0, Whh0, b0v, Wih1, Whh1, b1v, Wout);
    lstm_kernel<<<NBLK, NTH>>>(x, boutv, out);
}

// round 5
// speedup vs baseline: 2.1211x; 1.2956x over previous
#include <cuda_runtime.h>
#include <cstdint>

#define BB 32
#define TT 512
#define II 128
#define HH 1024
#define GG 4096
#define OO 128

#define NTH 256
#define NBLK 276
#define CH 64
#define RPAD 18    // u64 per reduction row: 16 data + 2 pad

// ---------------- device scratch ----------------
__device__ float Wp_ih0[II * GG];   // [k][n], n = j*4+g
__device__ float Wp_hh0[HH * GG];
__device__ float Wp_ih1[HH * GG];
__device__ float Wp_hh1[HH * GG];
__device__ float Wp_out[HH * OO];   // [k][o]
__device__ float gb0[GG];
__device__ float gb1[GG];
__device__ float h0s[2][HH][BB];    // layer0 hidden, transposed [j][b], double-buffered
__device__ float h2s[2][HH][BB];    // layer1 hidden
__device__ unsigned g_cnt;
__device__ unsigned g_flag;

// ---------------- prep: reset states/barrier + permute weights ----------------
__global__ void prep_kernel(const float* __restrict__ Wih0, const float* __restrict__ Whh0,
                            const float* __restrict__ b0v, const float* __restrict__ Wih1,
                            const float* __restrict__ Whh1, const float* __restrict__ b1v,
                            const float* __restrict__ Wout) {
    int idx0 = blockIdx.x * blockDim.x + threadIdx.x;
    int stride = gridDim.x * blockDim.x;
    if (idx0 == 0) { g_cnt = 0u; g_flag = 0u; }
    float* hz0 = &h0s[0][0][0];
    float* hz1 = &h2s[0][0][0];
    for (int i = idx0; i < 2 * HH * BB; i += stride) { hz0[i] = 0.f; hz1[i] = 0.f; }

    const int S0 = II * GG;
    const int S1 = HH * GG;
    const int S4 = HH * OO;
    const int total = S0 + 3 * S1 + S4 + 2 * GG;
    for (int idx = idx0; idx < total; idx += stride) {
        int r = idx;
        if (r < S0) {
            int k = r >> 12, n = r & (GG - 1);
            int g = n & 3, j = n >> 2;
            Wp_ih0[r] = Wih0[(g * HH + j) * II + k];
        } else if ((r -= S0) < S1) {
            int k = r >> 12, n = r & (GG - 1);
            int g = n & 3, j = n >> 2;
            Wp_hh0[r] = Whh0[(g * HH + j) * HH + k];
        } else if ((r -= S1) < S1) {
            int k = r >> 12, n = r & (GG - 1);
            int g = n & 3, j = n >> 2;
            Wp_ih1[r] = Wih1[(g * HH + j) * HH + k];
        } else if ((r -= S1) < S1) {
            int k = r >> 12, n = r & (GG - 1);
            int g = n & 3, j = n >> 2;
            Wp_hh1[r] = Whh1[(g * HH + j) * HH + k];
        } else if ((r -= S1) < S4) {
            Wp_out[r] = Wout[(r & (OO - 1)) * HH + (r >> 7)];
        } else if ((r -= S4) < GG) {
            gb0[r] = b0v[(r & 3) * HH + (r >> 2)];
        } else {
            r -= GG;
            gb1[r] = b1v[(r & 3) * HH + (r >> 2)];
        }
    }
}

// ---------------- packed fp32x2 ops + cp.async ----------------
#define FMA2(acc, a, b) asm("fma.rn.f32x2 %0, %1, %2, %0;" : "+l"(acc) : "l"(a), "l"(b))
#define ADD2(acc, a)    asm("add.rn.f32x2 %0, %0, %1;" : "+l"(acc) : "l"(a))
#define PACK2(d, v)     asm("mov.b64 %0, {%1, %1};" : "=l"(d) : "r"(v))

__device__ __forceinline__ void cpa16(uint32_t dst, const float* src) {
    asm volatile("cp.async.cg.shared.global [%0], [%1], 16;" :: "r"(dst), "l"(src));
}
#define CP_COMMIT() asm volatile("cp.async.commit_group;")
#define CP_WAIT1()  asm volatile("cp.async.wait_group 1;")
#define CP_WAIT0()  asm volatile("cp.async.wait_group 0;")

__device__ __forceinline__ float sigf(float x) { return 1.0f / (1.0f + __expf(-x)); }
__device__ __forceinline__ float tanhfast(float x) {
    return 1.0f - __fdividef(2.0f, __expf(2.0f * x) + 1.0f);
}
__device__ __forceinline__ float2 u2f(unsigned long long v) {
    float2 f;
    f.x = __uint_as_float((unsigned)v);
    f.y = __uint_as_float((unsigned)(v >> 32));
    return f;
}

// ---------------- grid barrier (sense/epoch) ----------------
__device__ __forceinline__ void grid_bar(int p) {
    if (threadIdx.x < 32) __threadfence();   // global writers are warp 0
    __syncthreads();
    if (threadIdx.x == 0) {
        unsigned tgt = (unsigned)(p + 1);
        unsigned old = atomicAdd(&g_cnt, 1u);
        if (old == tgt * NBLK - 1u) {
            asm volatile("st.global.release.gpu.u32 [%0], %1;" :: "l"(&g_flag), "r"(tgt) : "memory");
        } else {
            unsigned v;
            do {
                asm volatile("ld.global.acquire.gpu.u32 %0, [%1];" : "=r"(v) : "l"(&g_flag) : "memory");
                if (v >= tgt) break;
                __nanosleep(128);
            } while (true);
        }
    }
    __syncthreads();
}

// smem layout (floats): wbuf[s] at s*2048 (64k x 32n); hbuf[s] at 4096 + s*2048 (64k x 32b)
// reduction overlays the whole 9216-float region after the pipeline drains.

// ROLE 0 = layer0 (K = 128 x + 1024 h, NCH=18)
// ROLE 1 = layer1 (K = 1024 + 1024,    NCH=32)
// ROLE 2 = head   (K = 1024,           NCH=16)
template <int ROLE>
__device__ __forceinline__ void produce(int c, int t, int cg, float* smemf, uint32_t smem_b,
                                        const float* __restrict__ hA,
                                        const float* __restrict__ hB,
                                        const float* __restrict__ x) {
    const int tid = threadIdx.x;
    const int s = c & 1;
    const float* wbase;
    int wkoff;
    const float* hsrc = nullptr;
    int hkoff = 0;
    bool is_x = false;
    if (ROLE == 0) {
        if (c < 2) { wbase = Wp_ih0; wkoff = c * CH; is_x = true; }
        else       { wbase = Wp_hh0; wkoff = (c - 2) * CH; hsrc = hA; hkoff = (c - 2) * CH; }
    } else if (ROLE == 1) {
        if (c < 16) { wbase = Wp_ih1; wkoff = c * CH; hsrc = hA; hkoff = c * CH; }
        else        { wbase = Wp_hh1; wkoff = (c - 16) * CH; hsrc = hB; hkoff = (c - 16) * CH; }
    } else {
        wbase = Wp_out; wkoff = c * CH; hsrc = hB; hkoff = c * CH;
    }
    constexpr int WS = (ROLE == 2) ? OO : GG;

    const uint32_t wdst = smem_b + (unsigned)(s * 2048) * 4u;
    const uint32_t hdst = smem_b + (unsigned)(4096 + s * 2048) * 4u;

    // W chunk: 64 rows x 128B (the block's 32-col slice)
    {
        const float* wsrc = wbase + (size_t)wkoff * WS + cg * 32;
#pragma unroll
        for (int u = 0; u < 2; ++u) {
            int idx = tid + u * NTH;
            int row = idx >> 3, part = idx & 7;
            cpa16(wdst + (unsigned)(row * 32 + part * 4) * 4u,
                  wsrc + (size_t)row * WS + part * 4);
        }
    }
    if (ROLE == 0 && is_x) {
        // x chunk (transpose [b][k] -> [k][b]); plain LDG+STS, visible after syncthreads
        const int k4 = (tid & 15) * 4;
        const int bb0 = tid >> 4;
        float* hf = smemf + 4096 + s * 2048;
#pragma unroll
        for (int u = 0; u < 2; ++u) {
            int bb = bb0 + u * 16;
            const float4 v = __ldg(reinterpret_cast<const float4*>(
                x + (size_t)bb * TT * II + (size_t)t * II + c * CH + k4));
            hf[(k4 + 0) * 32 + bb] = v.x;
            hf[(k4 + 1) * 32 + bb] = v.y;
            hf[(k4 + 2) * 32 + bb] = v.z;
            hf[(k4 + 3) * 32 + bb] = v.w;
        }
    } else {
        // h chunk: contiguous 64 rows x 128B
        const float* hp = hsrc + (size_t)hkoff * BB;
#pragma unroll
        for (int u = 0; u < 2; ++u) {
            int idx = tid + u * NTH;
            cpa16(hdst + (unsigned)idx * 16u, hp + idx * 4);
        }
    }
}

template <int ROLE, int NCH>
__device__ __forceinline__ void do_pass(int p, int t, int cg, float* smemf, uint32_t smem_b,
                                        const float* __restrict__ x,
                                        const float* __restrict__ b_out,
                                        float* __restrict__ out,
                                        float* creg) {
    const int tid = threadIdx.x;
    const int ks = tid >> 5;          // warp index = k-split (8): k == ks (mod 8)
    const int lane = tid & 31;
    const int bg = lane >> 2;         // 8 batch groups of 4
    const int ng = lane & 3;          // 4 col groups of 8
    const int n0 = cg * 32 + ng * 8;
    const int b0 = bg * 4;
    const int par = p & 1, prev = par ^ 1;

    const float* __restrict__ hA = &h0s[prev][0][0];
    const float* __restrict__ hB = &h2s[prev][0][0];

    unsigned long long acc[4][4];
#pragma unroll
    for (int i = 0; i < 4; ++i)
#pragma unroll
        for (int j = 0; j < 4; ++j) acc[i][j] = 0ull;

    produce<ROLE>(0, t, cg, smemf, smem_b, hA, hB, x);
    CP_COMMIT();

    for (int c = 0; c < NCH; ++c) {
        if (c + 1 < NCH) {
            produce<ROLE>(c + 1, t, cg, smemf, smem_b, hA, hB, x);
            CP_COMMIT();
            CP_WAIT1();
        } else {
            CP_WAIT0();
        }
        __syncthreads();

        // consume chunk c from smem
        const float* wp = smemf + (c & 1) * 2048 + ks * 32 + ng * 8;
        const float* hp = smemf + 4096 + (c & 1) * 2048 + ks * 32 + bg * 4;
#pragma unroll
        for (int tt = 0; tt < CH / 8; ++tt) {
            ulonglong2 w0 = *reinterpret_cast<const ulonglong2*>(wp);
            ulonglong2 w1 = *reinterpret_cast<const ulonglong2*>(wp + 4);
            uint4 hq = *reinterpret_cast<const uint4*>(hp);
            unsigned long long hd0, hd1, hd2, hd3;
            PACK2(hd0, hq.x); PACK2(hd1, hq.y); PACK2(hd2, hq.z); PACK2(hd3, hq.w);
            FMA2(acc[0][0], w0.x, hd0); FMA2(acc[0][1], w0.x, hd1);
            FMA2(acc[0][2], w0.x, hd2); FMA2(acc[0][3], w0.x, hd3);
            FMA2(acc[1][0], w0.y, hd0); FMA2(acc[1][1], w0.y, hd1);
            FMA2(acc[1][2], w0.y, hd2); FMA2(acc[1][3], w0.y, hd3);
            FMA2(acc[2][0], w1.x, hd0); FMA2(acc[2][1], w1.x, hd1);
            FMA2(acc[2][2], w1.x, hd2); FMA2(acc[2][3], w1.x, hd3);
            FMA2(acc[3][0], w1.y, hd0); FMA2(acc[3][1], w1.y, hd1);
            FMA2(acc[3][2], w1.y, hd2); FMA2(acc[3][3], w1.y, hd3);
            wp += 8 * 32;
            hp += 8 * 32;
        }
        __syncthreads();
    }

    // ---- k-split reduction through smem (overlays stage buffers; pipeline drained) ----
    unsigned long long* red = reinterpret_cast<unsigned long long*>(smemf);
    unsigned long long* myrow = red + (size_t)tid * RPAD;
#pragma unroll
    for (int q = 0; q < 4; ++q) {
        ulonglong2 v0, v1;
        v0.x = acc[q][0]; v0.y = acc[q][1];
        v1.x = acc[q][2]; v1.y = acc[q][3];
        *reinterpret_cast<ulonglong2*>(myrow + q * 4) = v0;
        *reinterpret_cast<ulonglong2*>(myrow + q * 4 + 2) = v1;
    }
    __syncthreads();
    if (ks == 0) {
        unsigned long long s[16];
#pragma unroll
        for (int q = 0; q < 16; ++q) s[q] = 0ull;
#pragma unroll
        for (int w = 0; w < 8; ++w) {
            unsigned long long* rp = red + (size_t)(w * 32 + lane) * RPAD;
#pragma unroll
            for (int m = 0; m < 8; ++m) {
                ulonglong2 v = *reinterpret_cast<ulonglong2*>(rp + m * 2);
                ADD2(s[m * 2], v.x);
                ADD2(s[m * 2 + 1], v.y);
            }
        }
        // s[4q+bi]: col-pair q of {(i,f)j0,(g,o)j0,(i,f)j1,(g,o)j1}, batch b0+bi

        if (ROLE < 2) {
            const float* gbv = (ROLE == 0) ? gb0 : gb1;
            float* hdst = (ROLE == 0) ? &h0s[par][0][0] : &h2s[par][0][0];
            const int j0 = n0 >> 2;
#pragma unroll
            for (int jj = 0; jj < 2; ++jj) {
                float bi_ = gbv[n0 + jj * 4 + 0];
                float bf_ = gbv[n0 + jj * 4 + 1];
                float bg_ = gbv[n0 + jj * 4 + 2];
                float bo_ = gbv[n0 + jj * 4 + 3];
                float hv[4];
#pragma unroll
                for (int bi = 0; bi < 4; ++bi) {
                    float2 gif = u2f(s[(2 * jj) * 4 + bi]);      // (i, f)
                    float2 ggo = u2f(s[(2 * jj + 1) * 4 + bi]);  // (g, o)
                    float ig = sigf(gif.x + bi_);
                    float fg = sigf(gif.y + bf_);
                    float gt = tanhfast(ggo.x + bg_);
                    float og = sigf(ggo.y + bo_);
                    float cn = fg * creg[jj * 4 + bi] + ig * gt;
                    creg[jj * 4 + bi] = cn;
                    hv[bi] = og * tanhfast(cn);
                }
                float4 hq = make_float4(hv[0], hv[1], hv[2], hv[3]);
                __stcg(reinterpret_cast<float4*>(&hdst[(size_t)(j0 + jj) * BB + b0]), hq);
            }
        } else {
            float bo[8];
#pragma unroll
            for (int q = 0; q < 8; ++q) bo[q] = b_out[n0 + q];
#pragma unroll
            for (int bi = 0; bi < 4; ++bi) {
                float2 p0 = u2f(s[0 * 4 + bi]);
                float2 p1 = u2f(s[1 * 4 + bi]);
                float2 p2 = u2f(s[2 * 4 + bi]);
                float2 p3 = u2f(s[3 * 4 + bi]);
                float4 lo = make_float4(p0.x + bo[0], p0.y + bo[1], p1.x + bo[2], p1.y + bo[3]);
                float4 hi = make_float4(p2.x + bo[4], p2.y + bo[5], p3.x + bo[6], p3.y + bo[7]);
                float* op = out + ((size_t)(b0 + bi) * TT + t) * OO + n0;
                *reinterpret_cast<float4*>(op) = lo;
                *reinterpret_cast<float4*>(op + 4) = hi;
            }
        }
    }
}

// ---------------- persistent pipelined kernel ----------------
__global__ void __launch_bounds__(NTH, 2) lstm_kernel(const float* __restrict__ x,
                                                      const float* __restrict__ b_out,
                                                      float* __restrict__ out) {
    __shared__ __align__(16) float smemf[9216];   // 36,864 B: stage bufs 32KB + red overlay
    const int bid = blockIdx.x;
    const uint32_t smem_b = (uint32_t)__cvta_generic_to_shared(smemf);
    float creg[8];
#pragma unroll
    for (int i = 0; i < 8; ++i) creg[i] = 0.f;

    if (bid < 128) {
        // layer 0: t = p
        for (int p = 0; p < TT + 2; ++p) {
            if (p < TT) do_pass<0, 18>(p, p, bid, smemf, smem_b, x, b_out, out, creg);
            grid_bar(p);
        }
    } else if (bid < 132) {
        // head: t = p - 2
        for (int p = 0; p < TT + 2; ++p) {
            if (p >= 2) do_pass<2, 16>(p, p - 2, bid - 128, smemf, smem_b, x, b_out, out, creg);
            grid_bar(p);
        }
    } else if (bid < 148) {
        // idle (keeps barrier count uniform)
        for (int p = 0; p < TT + 2; ++p) grid_bar(p);
    } else {
        // layer 1: t = p - 1 (pairs with layer-0 block bid-148 on the same SM)
        for (int p = 0; p < TT + 2; ++p) {
            if (p >= 1 && p <= TT) do_pass<1, 32>(p, p - 1, bid - 148, smemf, smem_b, x, b_out, out, creg);
            grid_bar(p);
        }
    }
}

// ---------------- launch ----------------
extern "C" void kernel_launch(void* const* d_in, const int* in_sizes, int n_in,
                              void* d_out, int out_size) {
    const float* x     = (const float*)d_in[0];
    const float* Wih0  = (const float*)d_in[1];
    const float* Whh0  = (const float*)d_in[2];
    const float* b0v   = (const float*)d_in[3];
    const float* Wih1  = (const float*)d_in[4];
    const float* Whh1  = (const float*)d_in[5];
    const float* b1v   = (const float*)d_in[6];
    const float* Wout  = (const float*)d_in[7];
    const float* boutv = (const float*)d_in[8];
    float* out = (float*)d_out;

    prep_kernel<<<512, 256>>>(Wih0, Whh0, b0v, Wih1, Whh1, b1v, Wout);
    lstm_kernel<<<NBLK, NTH>>>(x, boutv, out);
}

// round 6
// speedup vs baseline: 2.5326x; 1.1940x over previous
#include <cuda_runtime.h>
#include <cstdint>

#define BB 32
#define TT 512
#define II 128
#define HH 1024
#define GG 4096
#define OO 128

#define NTH 256
#define NBLK 276
#define RPAD 18    // u64 per reduction row: 16 data + 2 pad
#define SMEM_BYTES 65536

// ---------------- device scratch ----------------
__device__ float Wp_ih0[II * GG];   // [k][n], n = j*4+g
__device__ float Wp_hh0[HH * GG];
__device__ float Wp_ih1[HH * GG];
__device__ float Wp_hh1[HH * GG];
__device__ float Wp_out[HH * OO];   // [k][o]
__device__ float gb0[GG];
__device__ float gb1[GG];
__device__ float xTg[TT * II * BB]; // x transposed: [t][k][b]
__device__ float h0s[2][HH][BB];    // layer0 hidden, transposed [j][b], double-buffered
__device__ float h2s[2][HH][BB];    // layer1 hidden
__device__ unsigned g_cnt;
__device__ unsigned g_flag;

// ---------------- prep: reset states/barrier + permute weights + transpose x ----------------
__global__ void prep_kernel(const float* __restrict__ xin,
                            const float* __restrict__ Wih0, const float* __restrict__ Whh0,
                            const float* __restrict__ b0v, const float* __restrict__ Wih1,
                            const float* __restrict__ Whh1, const float* __restrict__ b1v,
                            const float* __restrict__ Wout) {
    int idx0 = blockIdx.x * blockDim.x + threadIdx.x;
    int stride = gridDim.x * blockDim.x;
    if (idx0 == 0) { g_cnt = 0u; g_flag = 0u; }
    float* hz0 = &h0s[0][0][0];
    float* hz1 = &h2s[0][0][0];
    for (int i = idx0; i < 2 * HH * BB; i += stride) { hz0[i] = 0.f; hz1[i] = 0.f; }

    // transpose x: xT[t][k][b] = x[b][t][k]
    for (int i = idx0; i < TT * II * BB; i += stride) {
        int b = i & (BB - 1);
        int k = (i >> 5) & (II - 1);
        int t = i >> 12;
        xTg[i] = xin[((size_t)b * TT + t) * II + k];
    }

    const int S0 = II * GG;
    const int S1 = HH * GG;
    const int S4 = HH * OO;
    const int total = S0 + 3 * S1 + S4 + 2 * GG;
    for (int idx = idx0; idx < total; idx += stride) {
        int r = idx;
        if (r < S0) {
            int k = r >> 12, n = r & (GG - 1);
            int g = n & 3, j = n >> 2;
            Wp_ih0[r] = Wih0[(g * HH + j) * II + k];
        } else if ((r -= S0) < S1) {
            int k = r >> 12, n = r & (GG - 1);
            int g = n & 3, j = n >> 2;
            Wp_hh0[r] = Whh0[(g * HH + j) * HH + k];
        } else if ((r -= S1) < S1) {
            int k = r >> 12, n = r & (GG - 1);
            int g = n & 3, j = n >> 2;
            Wp_ih1[r] = Wih1[(g * HH + j) * HH + k];
        } else if ((r -= S1) < S1) {
            int k = r >> 12, n = r & (GG - 1);
            int g = n & 3, j = n >> 2;
            Wp_hh1[r] = Whh1[(g * HH + j) * HH + k];
        } else if ((r -= S1) < S4) {
            Wp_out[r] = Wout[(r & (OO - 1)) * HH + (r >> 7)];
        } else if ((r -= S4) < GG) {
            gb0[r] = b0v[(r & 3) * HH + (r >> 2)];
        } else {
            r -= GG;
            gb1[r] = b1v[(r & 3) * HH + (r >> 2)];
        }
    }
}

// ---------------- packed fp32x2 ops + cp.async ----------------
#define FMA2(acc, a, b) asm("fma.rn.f32x2 %0, %1, %2, %0;" : "+l"(acc) : "l"(a), "l"(b))
#define ADD2(acc, a)    asm("add.rn.f32x2 %0, %0, %1;" : "+l"(acc) : "l"(a))
#define PACK2(d, v)     asm("mov.b64 %0, {%1, %1};" : "=l"(d) : "r"(v))

__device__ __forceinline__ void cpa16(uint32_t dst, const float* src) {
    asm volatile("cp.async.cg.shared.global [%0], [%1], 16;" :: "r"(dst), "l"(src));
}
#define CP_COMMIT() asm volatile("cp.async.commit_group;")

__device__ __forceinline__ float sigf(float x) { return 1.0f / (1.0f + __expf(-x)); }
__device__ __forceinline__ float tanhfast(float x) {
    return 1.0f - __fdividef(2.0f, __expf(2.0f * x) + 1.0f);
}
__device__ __forceinline__ float2 u2f(unsigned long long v) {
    float2 f;
    f.x = __uint_as_float((unsigned)v);
    f.y = __uint_as_float((unsigned)(v >> 32));
    return f;
}

// ---------------- grid barrier (sense/epoch) ----------------
__device__ __forceinline__ void grid_bar(int p) {
    if (threadIdx.x < 32) __threadfence();   // global writers are warp 0
    __syncthreads();
    if (threadIdx.x == 0) {
        unsigned tgt = (unsigned)(p + 1);
        unsigned old = atomicAdd(&g_cnt, 1u);
        if (old == tgt * NBLK - 1u) {
            asm volatile("st.global.release.gpu.u32 [%0], %1;" :: "l"(&g_flag), "r"(tgt) : "memory");
        } else {
            unsigned v;
            do {
                asm volatile("ld.global.acquire.gpu.u32 %0, [%1];" : "=r"(v) : "l"(&g_flag) : "memory");
                if (v >= tgt) break;
                __nanosleep(128);
            } while (true);
        }
    }
    __syncthreads();
}

// smem: per-warp private region of 2048 floats at wid*2048.
//   stage buf (0..3): w at buf*512 (8 rows x 32n), h at buf*512+256 (8 rows x 32b)
// Reduction overlays smem[0 .. 256*RPAD u64) after a __syncthreads.

// ROLE 0 = layer0 (K=1152: 128 x + 1024 h), ROLE 1 = layer1 (K=2048), ROLE 2 = head (K=1024)
template <int ROLE>
__device__ __forceinline__ void produce(int s, int t, int cg, int base_k,
                                        uint32_t warp_sm,
                                        const float* __restrict__ hA,
                                        const float* __restrict__ hB) {
    const int lane = threadIdx.x & 31;
    const int kg = base_k + s * 8;
    const float* wsrc;
    const float* hsrc;
    constexpr int WS = (ROLE == 2) ? OO : GG;
    if (ROLE == 0) {
        if (kg < II) { wsrc = Wp_ih0 + (size_t)kg * GG; hsrc = xTg + ((size_t)t * II + kg) * BB; }
        else         { wsrc = Wp_hh0 + (size_t)(kg - II) * GG; hsrc = hA + (size_t)(kg - II) * BB; }
    } else if (ROLE == 1) {
        if (kg < HH) { wsrc = Wp_ih1 + (size_t)kg * GG; hsrc = hA + (size_t)kg * BB; }
        else         { wsrc = Wp_hh1 + (size_t)(kg - HH) * GG; hsrc = hB + (size_t)(kg - HH) * BB; }
    } else {
        wsrc = Wp_out + (size_t)kg * OO; hsrc = hB + (size_t)kg * BB;
    }
    wsrc += cg * 32;

    const uint32_t wd = warp_sm + (unsigned)((s & 3) * 512) * 4u;
    const uint32_t hd = wd + 1024u;
#pragma unroll
    for (int u2 = 0; u2 < 2; ++u2) {
        int u = lane + u2 * 32;
        int row = u >> 3, part = u & 7;
        cpa16(wd + (unsigned)(row * 32 + part * 4) * 4u, wsrc + (size_t)row * WS + part * 4);
        cpa16(hd + (unsigned)u * 16u, hsrc + u * 4);
    }
}

template <int ROLE, int NS>
__device__ __forceinline__ void do_pass(int p, int t, int cg, float* smemf, uint32_t smem_b,
                                        const float* __restrict__ b_out,
                                        float* __restrict__ out,
                                        float* creg) {
    const int tid = threadIdx.x;
    const int ks = tid >> 5;          // warp index = contiguous k-split (8)
    const int lane = tid & 31;
    const int bg = lane >> 2;         // 8 batch groups of 4
    const int ng = lane & 3;          // 4 col groups of 8
    const int n0 = cg * 32 + ng * 8;
    const int b0 = bg * 4;
    const int par = p & 1, prev = par ^ 1;
    const int base_k = ks * NS * 8;

    const float* __restrict__ hA = &h0s[prev][0][0];
    const float* __restrict__ hB = &h2s[prev][0][0];

    const uint32_t warp_sm = smem_b + (unsigned)(ks * 2048) * 4u;
    const float* warp_f = smemf + ks * 2048;

    unsigned long long acc[4][4];
#pragma unroll
    for (int i = 0; i < 4; ++i)
#pragma unroll
        for (int j = 0; j < 4; ++j) acc[i][j] = 0ull;

    // prologue: 3 stages in flight
    produce<ROLE>(0, t, cg, base_k, warp_sm, hA, hB); CP_COMMIT();
    produce<ROLE>(1, t, cg, base_k, warp_sm, hA, hB); CP_COMMIT();
    produce<ROLE>(2, t, cg, base_k, warp_sm, hA, hB); CP_COMMIT();

    for (int s = 0; s < NS; ++s) {
        if (s + 3 < NS) {
            produce<ROLE>(s + 3, t, cg, base_k, warp_sm, hA, hB);
            CP_COMMIT();
            asm volatile("cp.async.wait_group 3;");
        } else {
            int rem = NS - 1 - s;
            if (rem == 2)      asm volatile("cp.async.wait_group 2;");
            else if (rem == 1) asm volatile("cp.async.wait_group 1;");
            else               asm volatile("cp.async.wait_group 0;");
        }
        __syncwarp();

        const float* wp = warp_f + (s & 3) * 512 + ng * 8;
        const float* hp = warp_f + (s & 3) * 512 + 256 + bg * 4;
#pragma unroll
        for (int r = 0; r < 8; ++r) {
            ulonglong2 w0 = *reinterpret_cast<const ulonglong2*>(wp);
            ulonglong2 w1 = *reinterpret_cast<const ulonglong2*>(wp + 4);
            uint4 hq = *reinterpret_cast<const uint4*>(hp);
            unsigned long long hd0, hd1, hd2, hd3;
            PACK2(hd0, hq.x); PACK2(hd1, hq.y); PACK2(hd2, hq.z); PACK2(hd3, hq.w);
            FMA2(acc[0][0], w0.x, hd0); FMA2(acc[0][1], w0.x, hd1);
            FMA2(acc[0][2], w0.x, hd2); FMA2(acc[0][3], w0.x, hd3);
            FMA2(acc[1][0], w0.y, hd0); FMA2(acc[1][1], w0.y, hd1);
            FMA2(acc[1][2], w0.y, hd2); FMA2(acc[1][3], w0.y, hd3);
            FMA2(acc[2][0], w1.x, hd0); FMA2(acc[2][1], w1.x, hd1);
            FMA2(acc[2][2], w1.x, hd2); FMA2(acc[2][3], w1.x, hd3);
            FMA2(acc[3][0], w1.y, hd0); FMA2(acc[3][1], w1.y, hd1);
            FMA2(acc[3][2], w1.y, hd2); FMA2(acc[3][3], w1.y, hd3);
            wp += 32;
            hp += 32;
        }
    }

    // ---- k-split reduction (overlay; all warps must be done with stage buffers) ----
    __syncthreads();
    unsigned long long* red = reinterpret_cast<unsigned long long*>(smemf);
    unsigned long long* myrow = red + (size_t)tid * RPAD;
#pragma unroll
    for (int q = 0; q < 4; ++q) {
        ulonglong2 v0, v1;
        v0.x = acc[q][0]; v0.y = acc[q][1];
        v1.x = acc[q][2]; v1.y = acc[q][3];
        *reinterpret_cast<ulonglong2*>(myrow + q * 4) = v0;
        *reinterpret_cast<ulonglong2*>(myrow + q * 4 + 2) = v1;
    }
    __syncthreads();
    if (ks == 0) {
        unsigned long long s[16];
#pragma unroll
        for (int q = 0; q < 16; ++q) s[q] = 0ull;
#pragma unroll
        for (int w = 0; w < 8; ++w) {
            unsigned long long* rp = red + (size_t)(w * 32 + lane) * RPAD;
#pragma unroll
            for (int m = 0; m < 8; ++m) {
                ulonglong2 v = *reinterpret_cast<ulonglong2*>(rp + m * 2);
                ADD2(s[m * 2], v.x);
                ADD2(s[m * 2 + 1], v.y);
            }
        }
        // s[4q+bi]: col-pair q of {(i,f)j0,(g,o)j0,(i,f)j1,(g,o)j1}, batch b0+bi

        if (ROLE < 2) {
            const float* gbv = (ROLE == 0) ? gb0 : gb1;
            float* hdst = (ROLE == 0) ? &h0s[par][0][0] : &h2s[par][0][0];
            const int j0 = n0 >> 2;
#pragma unroll
            for (int jj = 0; jj < 2; ++jj) {
                float bi_ = gbv[n0 + jj * 4 + 0];
                float bf_ = gbv[n0 + jj * 4 + 1];
                float bg_ = gbv[n0 + jj * 4 + 2];
                float bo_ = gbv[n0 + jj * 4 + 3];
                float hv[4];
#pragma unroll
                for (int bi = 0; bi < 4; ++bi) {
                    float2 gif = u2f(s[(2 * jj) * 4 + bi]);      // (i, f)
                    float2 ggo = u2f(s[(2 * jj + 1) * 4 + bi]);  // (g, o)
                    float ig = sigf(gif.x + bi_);
                    float fg = sigf(gif.y + bf_);
                    float gt = tanhfast(ggo.x + bg_);
                    float og = sigf(ggo.y + bo_);
                    float cn = fg * creg[jj * 4 + bi] + ig * gt;
                    creg[jj * 4 + bi] = cn;
                    hv[bi] = og * tanhfast(cn);
                }
                float4 hq = make_float4(hv[0], hv[1], hv[2], hv[3]);
                __stcg(reinterpret_cast<float4*>(&hdst[(size_t)(j0 + jj) * BB + b0]), hq);
            }
        } else {
            float bo[8];
#pragma unroll
            for (int q = 0; q < 8; ++q) bo[q] = b_out[n0 + q];
#pragma unroll
            for (int bi = 0; bi < 4; ++bi) {
                float2 p0 = u2f(s[0 * 4 + bi]);
                float2 p1 = u2f(s[1 * 4 + bi]);
                float2 p2 = u2f(s[2 * 4 + bi]);
                float2 p3 = u2f(s[3 * 4 + bi]);
                float4 lo = make_float4(p0.x + bo[0], p0.y + bo[1], p1.x + bo[2], p1.y + bo[3]);
                float4 hi = make_float4(p2.x + bo[4], p2.y + bo[5], p3.x + bo[6], p3.y + bo[7]);
                float* op = out + ((size_t)(b0 + bi) * TT + t) * OO + n0;
                *reinterpret_cast<float4*>(op) = lo;
                *reinterpret_cast<float4*>(op + 4) = hi;
            }
        }
    }
}

// ---------------- persistent pipelined kernel ----------------
extern __shared__ float smemf[];

__global__ void __launch_bounds__(NTH, 2) lstm_kernel(const float* __restrict__ b_out,
                                                      float* __restrict__ out) {
    const int bid = blockIdx.x;
    const uint32_t smem_b = (uint32_t)__cvta_generic_to_shared(smemf);
    float creg[8];
#pragma unroll
    for (int i = 0; i < 8; ++i) creg[i] = 0.f;

    if (bid < 128) {
        // layer 0: t = p; K=1152, 18 stages/warp
        for (int p = 0; p < TT + 2; ++p) {
            if (p < TT) do_pass<0, 18>(p, p, bid, smemf, smem_b, b_out, out, creg);
            grid_bar(p);
        }
    } else if (bid < 132) {
        // head: t = p - 2; K=1024, 16 stages/warp
        for (int p = 0; p < TT + 2; ++p) {
            if (p >= 2) do_pass<2, 16>(p, p - 2, bid - 128, smemf, smem_b, b_out, out, creg);
            grid_bar(p);
        }
    } else if (bid < 148) {
        // idle (keeps barrier count uniform)
        for (int p = 0; p < TT + 2; ++p) grid_bar(p);
    } else {
        // layer 1: t = p - 1; K=2048, 32 stages/warp (pairs with layer-0 block bid-148 on same SM)
        for (int p = 0; p < TT + 2; ++p) {
            if (p >= 1 && p <= TT) do_pass<1, 32>(p, p - 1, bid - 148, smemf, smem_b, b_out, out, creg);
            grid_bar(p);
        }
    }
}

// ---------------- launch ----------------
extern "C" void kernel_launch(void* const* d_in, const int* in_sizes, int n_in,
                              void* d_out, int out_size) {
    const float* x     = (const float*)d_in[0];
    const float* Wih0  = (const float*)d_in[1];
    const float* Whh0  = (const float*)d_in[2];
    const float* b0v   = (const float*)d_in[3];
    const float* Wih1  = (const float*)d_in[4];
    const float* Whh1  = (const float*)d_in[5];
    const float* b1v   = (const float*)d_in[6];
    const float* Wout  = (const float*)d_in[7];
    const float* boutv = (const float*)d_in[8];
    float* out = (float*)d_out;

    static bool attr_set = false;
    if (!attr_set) {
        cudaFuncSetAttribute(lstm_kernel, cudaFuncAttributeMaxDynamicSharedMemorySize, SMEM_BYTES);
        attr_set = true;
    }

    prep_kernel<<<512, 256>>>(x, Wih0, Whh0, b0v, Wih1, Whh1, b1v, Wout);
    lstm_kernel<<<NBLK, NTH, SMEM_BYTES>>>(boutv, out);
}